// round 14
// baseline (speedup 1.0000x reference)
#include <cuda_runtime.h>

#define B_N 128
#define S_N 1024
#define T_N 128
#define NTH 128
#define SOS_T 0
#define EOS_T 1

__device__ float g_res[B_N];

typedef unsigned long long u64;

static __device__ __forceinline__ u64 fma2(u64 a, u64 b, u64 c) {
    u64 d; asm("fma.rn.f32x2 %0, %1, %2, %3;" : "=l"(d) : "l"(a), "l"(b), "l"(c)); return d;
}
static __device__ __forceinline__ u64 add2(u64 a, u64 b) {
    u64 d; asm("add.rn.f32x2 %0, %1, %2;" : "=l"(d) : "l"(a), "l"(b)); return d;
}
static __device__ __forceinline__ u64 pk2(float x, float y) {
    u64 r; asm("mov.b64 %0, {%1,%2};" : "=l"(r) : "f"(x), "f"(y)); return r;
}
static __device__ __forceinline__ void upk2(u64 v, float &x, float &y) {
    asm("mov.b64 {%0,%1}, %2;" : "=f"(x), "=f"(y) : "l"(v));
}
static __device__ __forceinline__ float ex2a(float x) {
    float r; asm("ex2.approx.f32 %0, %1;" : "=f"(r) : "f"(x)); return r;
}
static __device__ __forceinline__ float lg2a(float x) {
    float r; asm("lg2.approx.f32 %0, %1;" : "=f"(r) : "f"(x)); return r;
}

// One CTA per batch, 128 threads, thread j owns column j of alpha.
// Linear-space recurrence. Thread j==2 publishes its raw wp each step; every
// thread rebuilds the normalizer chain M_{s+1} = M_{s-1} + ln(wp_pub_{s-1})
// at the TOP of the step (thread-uniform, overlapped with the matvec).
// Alpha bookkeeping (lg2) deferred one step; pre-barrier critical path is
// add-tree -> fmax -> FMUL -> STS.  (R6 structure — best measured: 223.3 us.)
__global__ void __launch_bounds__(NTH, 1) crf_fwd(
    const float* __restrict__ em, const float* __restrict__ tr,
    const float* __restrict__ mk, const int* __restrict__ tg)
{
    const int b = blockIdx.x;
    const int j = threadIdx.x;

    __shared__ __align__(16) float s_v[2][T_N];   // exp(alpha - M), double buffered
    __shared__ float s_wp[2];                     // published wp[2], double buffered
    __shared__ __align__(16) float s_red[NTH];
    __shared__ int   s_cnt4[4];
    __shared__ float s_red4[4];
    __shared__ float s_score;

    const float* emb = em + (size_t)b * S_N * T_N;
    const float* mkb = mk + (size_t)b * S_N;
    const int*   tgb = tg + (size_t)b * S_N;

    const float L2E = 1.4426950408889634f;
    const float LN2 = 0.6931471805599453f;

    // ---------------- gold path score (warp-shuffle reduce) ----------------
    {
        float sp = 0.f; int cnt = 0;
        for (int s = j; s < S_N; s += NTH) {
            float mv = mkb[s];
            cnt += (int)mv;
            if (s >= 1) {
                int t1  = tgb[s];
                int t0p = tgb[s - 1];
                sp += (emb[(size_t)s * T_N + t1] + tr[t0p * T_N + t1]) * mv;
            }
        }
        #pragma unroll
        for (int msk = 16; msk >= 1; msk >>= 1) {
            sp  += __shfl_xor_sync(0xffffffffu, sp, msk);
            cnt += __shfl_xor_sync(0xffffffffu, cnt, msk);
        }
        if ((j & 31) == 0) { s_red4[j >> 5] = sp; s_cnt4[j >> 5] = cnt; }
        __syncthreads();
        if (j == 0) {
            float spt = s_red4[0] + s_red4[1] + s_red4[2] + s_red4[3];
            int   ct  = s_cnt4[0] + s_cnt4[1] + s_cnt4[2] + s_cnt4[3];
            int last = ct - 1;
            int t0   = tgb[0];
            int lt   = tgb[last];
            s_score = spt + tr[SOS_T * T_N + t0] + emb[t0] + tr[lt * T_N + EOS_T];
        }
    }

    // ---------------- transition column in registers (exp domain) ----------------
    // E[p] packs expT[2p][j], expT[2p+1][j]  (all 128 source states).
    u64 E[64];
    #pragma unroll
    for (int p = 0; p < 64; p++) {
        float a = ex2a(tr[(2 * p)     * T_N + j] * L2E);
        float c = ex2a(tr[(2 * p + 1) * T_N + j] * L2E);
        E[p] = pk2(a, c);
    }

    // ---------------- alpha0, m0, v0 ----------------
    float alpha = tr[SOS_T * T_N + j] + emb[j];
    s_red[j] = alpha;
    __syncthreads();
    if (j < 32) {
        float mx = fmaxf(fmaxf(s_red[j], s_red[j + 32]),
                         fmaxf(s_red[j + 64], s_red[j + 96]));
        #pragma unroll
        for (int msk = 16; msk >= 1; msk >>= 1)
            mx = fmaxf(mx, __shfl_xor_sync(0xffffffffu, mx, msk));
        if (j == 0) s_red[0] = mx;   // broadcast m0
    }
    __syncthreads();
    const float m0 = s_red[0];
    // M chain: M_cur = M_1 = m0; M_prev seeds M_2 = M_prev + ln(1) = m0.
    float M_prev = m0, M_cur = m0;
    s_v[1][j] = ex2a((alpha - m0) * L2E);   // step 1 reads buffer 1
    if (j == 0) s_wp[0] = 1.0f;             // step 1 reads slot 0

    // emission/mask register prefetch, distance 3
    float eA = emb[(size_t)1 * T_N + j];  float mA = mkb[1];
    float eB = emb[(size_t)2 * T_N + j];  float mB = mkb[2];
    float eC = emb[(size_t)3 * T_N + j];  float mC = mkb[3];

    // deferred-alpha state (step 0 already final: mP = 0 -> no-op update)
    float wp_prev = 1.0f, eP = 0.0f, mP = 0.0f, MP = m0;
    __syncthreads();

    // ---------------- recurrence: 1023 sequential steps ----------------
    for (int s = 1; s < S_N; s++) {
        // independent LDGs first: in flight before the dependent MUFU chain
        int sp3 = (s + 3 < S_N) ? (s + 3) : (S_N - 1);
        float eN = emb[(size_t)sp3 * T_N + j];
        float mN = mkb[sp3];

        // ===== overlapped top section (hidden under the matvec) =====
        float wp_pub = s_wp[(s - 1) & 1];
        float M_next = fmaf(lg2a(wp_pub), LN2, M_prev);  // M_{s+1}, thread-uniform
        // deferred alpha update for step s-1
        float anew_p = fmaf(lg2a(wp_prev), LN2, MP) + eP;
        alpha = fmaf(mP, anew_p - alpha, alpha);         // alpha_{s-1}
        float Kf    = ex2a((M_cur + eA - M_next) * L2E); // exp(M_s + e_s - M_{s+1})
        float v_old = ex2a((alpha - M_next) * L2E);      // mask==0 fallback

        // ===== matvec over ALL 128 states: wp = sum_i v[i]*expT[i][j] =====
        const ulonglong2* v2 = (const ulonglong2*)s_v[s & 1];
        u64 a0 = 0ull, a1 = 0ull, a2 = 0ull, a3 = 0ull;
        u64 a4 = 0ull, a5 = 0ull, a6 = 0ull, a7 = 0ull;
        #pragma unroll
        for (int k = 0; k < 16; k++) {
            ulonglong2 p = v2[2 * k];
            ulonglong2 q = v2[2 * k + 1];
            if ((k & 1) == 0) {
                a0 = fma2(E[4 * k + 0], p.x, a0);
                a1 = fma2(E[4 * k + 1], p.y, a1);
                a2 = fma2(E[4 * k + 2], q.x, a2);
                a3 = fma2(E[4 * k + 3], q.y, a3);
            } else {
                a4 = fma2(E[4 * k + 0], p.x, a4);
                a5 = fma2(E[4 * k + 1], p.y, a5);
                a6 = fma2(E[4 * k + 2], q.x, a6);
                a7 = fma2(E[4 * k + 3], q.y, a7);
            }
        }
        u64 t0 = add2(add2(a0, a1), add2(a2, a3));
        u64 t1 = add2(add2(a4, a5), add2(a6, a7));
        u64 tt = add2(t0, t1);
        float tx, ty; upk2(tt, tx, ty);
        float wp = fmaxf(tx + ty, 1e-33f);   // SOS column sums to 0; keep finite

        // ===== short pre-barrier tail =====
        float v_new = (mA != 0.f) ? (wp * Kf) : v_old;
        s_v[(s + 1) & 1][j] = v_new;
        if (j == 2) s_wp[s & 1] = wp;        // publish raw wp for M_{s+2}

        // save deferred state, shift pipelines
        wp_prev = wp; eP = eA; mP = mA; MP = M_cur;
        M_prev = M_cur; M_cur = M_next;
        eA = eB; eB = eC; eC = eN;
        mA = mB; mB = mC; mC = mN;
        __syncthreads();
    }

    // final deferred alpha update (step S_N-1)
    {
        float anew_p = fmaf(lg2a(wp_prev), LN2, MP) + eP;
        alpha = fmaf(mP, anew_p - alpha, alpha);
    }

    // ---------------- partition + per-batch result ----------------
    {
        s_red[j] = alpha + tr[j * T_N + EOS_T];
        __syncthreads();
        if (j < 32) {
            float z0 = s_red[j], z1 = s_red[j + 32], z2 = s_red[j + 64], z3 = s_red[j + 96];
            float mx = fmaxf(fmaxf(z0, z1), fmaxf(z2, z3));
            #pragma unroll
            for (int msk = 16; msk >= 1; msk >>= 1)
                mx = fmaxf(mx, __shfl_xor_sync(0xffffffffu, mx, msk));
            float sm = ex2a((z0 - mx) * L2E) + ex2a((z1 - mx) * L2E)
                     + ex2a((z2 - mx) * L2E) + ex2a((z3 - mx) * L2E);
            #pragma unroll
            for (int msk = 16; msk >= 1; msk >>= 1)
                sm += __shfl_xor_sync(0xffffffffu, sm, msk);
            if (j == 0) {
                float partition = mx + lg2a(sm) * LN2;
                g_res[b] = s_score - partition;
            }
        }
    }
}

__global__ void crf_reduce(float* out) {
    int tid = threadIdx.x;  // 128 threads
    __shared__ float sh[4];
    float v = g_res[tid];
    #pragma unroll
    for (int msk = 16; msk >= 1; msk >>= 1)
        v += __shfl_xor_sync(0xffffffffu, v, msk);
    if ((tid & 31) == 0) sh[tid >> 5] = v;
    __syncthreads();
    if (tid == 0) out[0] = -(sh[0] + sh[1] + sh[2] + sh[3]);
}

extern "C" void kernel_launch(void* const* d_in, const int* in_sizes, int n_in,
                              void* d_out, int out_size) {
    (void)in_sizes; (void)n_in; (void)out_size;
    const float* em = (const float*)d_in[0];   // emissions [128,1024,128] f32
    const float* tr = (const float*)d_in[1];   // transition [128,128] f32
    const float* mk = (const float*)d_in[2];   // mask [128,1024] f32
    const int*   tg = (const int*)d_in[3];     // tags [128,1024] i32
    crf_fwd<<<B_N, NTH>>>(em, tr, mk, tg);
    crf_reduce<<<1, B_N>>>((float*)d_out);
}

// round 15
// speedup vs baseline: 1.0639x; 1.0639x over previous
#include <cuda_runtime.h>

#define B_N 128
#define S_N 1024
#define T_N 128
#define NTH 128
#define SOS_T 0
#define EOS_T 1

__device__ float g_res[B_N];

typedef unsigned long long u64;

static __device__ __forceinline__ u64 fma2(u64 a, u64 b, u64 c) {
    u64 d; asm("fma.rn.f32x2 %0, %1, %2, %3;" : "=l"(d) : "l"(a), "l"(b), "l"(c)); return d;
}
static __device__ __forceinline__ u64 add2(u64 a, u64 b) {
    u64 d; asm("add.rn.f32x2 %0, %1, %2;" : "=l"(d) : "l"(a), "l"(b)); return d;
}
static __device__ __forceinline__ u64 pk2(float x, float y) {
    u64 r; asm("mov.b64 %0, {%1,%2};" : "=l"(r) : "f"(x), "f"(y)); return r;
}
static __device__ __forceinline__ void upk2(u64 v, float &x, float &y) {
    asm("mov.b64 {%0,%1}, %2;" : "=f"(x), "=f"(y) : "l"(v));
}
static __device__ __forceinline__ float ex2a(float x) {
    float r; asm("ex2.approx.f32 %0, %1;" : "=f"(r) : "f"(x)); return r;
}
static __device__ __forceinline__ float lg2a(float x) {
    float r; asm("lg2.approx.f32 %0, %1;" : "=f"(r) : "f"(x)); return r;
}

// One CTA per batch, 128 threads, thread j owns column j of alpha.
// Linear-space recurrence. Normalizer chain: thread 2 publishes its raw wp each
// step; every thread reconstructs M_{s+1} = M_{s-1} + ln(wp_pub_{s-1}) at the
// TOP of step s (identical computation in all threads -> consistent chain,
// overlapped with the matvec). Alpha bookkeeping (lg2) is deferred one step,
// so the pre-barrier critical path is add-tree -> fmax -> FMUL -> STS.
__global__ void __launch_bounds__(NTH, 1) crf_fwd(
    const float* __restrict__ em, const float* __restrict__ tr,
    const float* __restrict__ mk, const int* __restrict__ tg)
{
    const int b = blockIdx.x;
    const int j = threadIdx.x;

    __shared__ __align__(16) float s_v[2][T_N];   // exp(alpha - M), double buffered
    __shared__ float s_wp[2];                     // published wp[2], double buffered
    __shared__ __align__(16) float s_red[NTH];
    __shared__ int   s_cnt[NTH];
    __shared__ float s_score;

    const float* emb = em + (size_t)b * S_N * T_N;
    const float* mkb = mk + (size_t)b * S_N;
    const int*   tgb = tg + (size_t)b * S_N;

    const float L2E = 1.4426950408889634f;
    const float LN2 = 0.6931471805599453f;

    // ---------------- gold path score ----------------
    {
        float sp = 0.f; int cnt = 0;
        for (int s = j; s < S_N; s += NTH) {
            float mv = mkb[s];
            cnt += (int)mv;
            if (s >= 1) {
                int t1  = tgb[s];
                int t0p = tgb[s - 1];
                sp += (emb[(size_t)s * T_N + t1] + tr[t0p * T_N + t1]) * mv;
            }
        }
        s_red[j] = sp; s_cnt[j] = cnt;
        __syncthreads();
        for (int st = NTH >> 1; st > 0; st >>= 1) {
            if (j < st) { s_red[j] += s_red[j + st]; s_cnt[j] += s_cnt[j + st]; }
            __syncthreads();
        }
        if (j == 0) {
            int last = s_cnt[0] - 1;
            int t0   = tgb[0];
            int lt   = tgb[last];
            s_score = s_red[0] + tr[SOS_T * T_N + t0] + emb[t0] + tr[lt * T_N + EOS_T];
        }
        __syncthreads();
    }

    // ---------------- transition column in registers (exp domain) ----------------
    // E[p] packs expT[2p][j], expT[2p+1][j]  (all 128 source states).
    u64 E[64];
    #pragma unroll
    for (int p = 0; p < 64; p++) {
        float a = ex2a(tr[(2 * p)     * T_N + j] * L2E);
        float c = ex2a(tr[(2 * p + 1) * T_N + j] * L2E);
        E[p] = pk2(a, c);
    }

    // ---------------- alpha0, m0, v0 ----------------
    float alpha = tr[SOS_T * T_N + j] + emb[j];
    s_red[j] = alpha;
    __syncthreads();
    if (j < 32) {
        float mx = fmaxf(fmaxf(s_red[j], s_red[j + 32]),
                         fmaxf(s_red[j + 64], s_red[j + 96]));
        #pragma unroll
        for (int msk = 16; msk >= 1; msk >>= 1)
            mx = fmaxf(mx, __shfl_xor_sync(0xffffffffu, mx, msk));
        if (j == 0) s_red[0] = mx;   // reuse s_red[0] to broadcast m0
    }
    __syncthreads();
    const float m0 = s_red[0];
    // M chain: M_cur = M_1 = m0; M_prev seeds M_2 = M_prev + ln(1) = m0.
    float M_prev = m0, M_cur = m0;
    s_v[1][j] = ex2a((alpha - m0) * L2E);   // step 1 reads buffer 1
    if (j == 0) s_wp[0] = 1.0f;             // step 1 reads slot 0

    // emission/mask register prefetch, distance 3
    float eA = emb[(size_t)1 * T_N + j];  float mA = mkb[1];
    float eB = emb[(size_t)2 * T_N + j];  float mB = mkb[2];
    float eC = emb[(size_t)3 * T_N + j];  float mC = mkb[3];

    // deferred-alpha state (step 0 already final: mP = 0 -> no-op update)
    float wp_prev = 1.0f, eP = 0.0f, mP = 0.0f, MP = m0;
    __syncthreads();

    // ---------------- recurrence: 1023 sequential steps ----------------
    for (int s = 1; s < S_N; s++) {
        // ===== overlapped top section (hidden under the matvec) =====
        float wp_pub = s_wp[(s - 1) & 1];
        float M_next = fmaf(lg2a(wp_pub), LN2, M_prev);  // M_{s+1}, thread-uniform
        // deferred alpha update for step s-1
        float anew_p = fmaf(lg2a(wp_prev), LN2, MP) + eP;
        alpha = fmaf(mP, anew_p - alpha, alpha);         // alpha_{s-1}
        float Kf    = ex2a((M_cur + eA - M_next) * L2E); // exp(M_s + e_s - M_{s+1})
        float v_old = ex2a((alpha - M_next) * L2E);      // mask==0 fallback
        int sp3 = (s + 3 < S_N) ? (s + 3) : (S_N - 1);
        float eN = emb[(size_t)sp3 * T_N + j];
        float mN = mkb[sp3];

        // ===== matvec over ALL 128 states: wp = sum_i v[i]*expT[i][j] =====
        const ulonglong2* v2 = (const ulonglong2*)s_v[s & 1];
        u64 a0 = 0ull, a1 = 0ull, a2 = 0ull, a3 = 0ull;
        u64 a4 = 0ull, a5 = 0ull, a6 = 0ull, a7 = 0ull;
        #pragma unroll
        for (int k = 0; k < 16; k++) {
            ulonglong2 p = v2[2 * k];
            ulonglong2 q = v2[2 * k + 1];
            if ((k & 1) == 0) {
                a0 = fma2(E[4 * k + 0], p.x, a0);
                a1 = fma2(E[4 * k + 1], p.y, a1);
                a2 = fma2(E[4 * k + 2], q.x, a2);
                a3 = fma2(E[4 * k + 3], q.y, a3);
            } else {
                a4 = fma2(E[4 * k + 0], p.x, a4);
                a5 = fma2(E[4 * k + 1], p.y, a5);
                a6 = fma2(E[4 * k + 2], q.x, a6);
                a7 = fma2(E[4 * k + 3], q.y, a7);
            }
        }
        u64 t0 = add2(add2(a0, a1), add2(a2, a3));
        u64 t1 = add2(add2(a4, a5), add2(a6, a7));
        u64 tt = add2(t0, t1);
        float tx, ty; upk2(tt, tx, ty);
        float wp = fmaxf(tx + ty, 1e-33f);   // SOS column sums to 0; keep finite

        // ===== short pre-barrier tail =====
        float v_new = (mA != 0.f) ? (wp * Kf) : v_old;
        s_v[(s + 1) & 1][j] = v_new;
        if (j == 2) s_wp[s & 1] = wp;        // publish raw wp for M_{s+2}

        // save deferred state, shift pipelines
        wp_prev = wp; eP = eA; mP = mA; MP = M_cur;
        M_prev = M_cur; M_cur = M_next;
        eA = eB; eB = eC; eC = eN;
        mA = mB; mB = mC; mC = mN;
        __syncthreads();
    }

    // final deferred alpha update (step S_N-1)
    {
        float anew_p = fmaf(lg2a(wp_prev), LN2, MP) + eP;
        alpha = fmaf(mP, anew_p - alpha, alpha);
    }

    // ---------------- partition + per-batch result ----------------
    {
        s_red[j] = alpha + tr[j * T_N + EOS_T];
        __syncthreads();
        if (j < 32) {
            float z0 = s_red[j], z1 = s_red[j + 32], z2 = s_red[j + 64], z3 = s_red[j + 96];
            float mx = fmaxf(fmaxf(z0, z1), fmaxf(z2, z3));
            #pragma unroll
            for (int msk = 16; msk >= 1; msk >>= 1)
                mx = fmaxf(mx, __shfl_xor_sync(0xffffffffu, mx, msk));
            float sm = ex2a((z0 - mx) * L2E) + ex2a((z1 - mx) * L2E)
                     + ex2a((z2 - mx) * L2E) + ex2a((z3 - mx) * L2E);
            #pragma unroll
            for (int msk = 16; msk >= 1; msk >>= 1)
                sm += __shfl_xor_sync(0xffffffffu, sm, msk);
            if (j == 0) {
                float partition = mx + lg2a(sm) * LN2;
                g_res[b] = s_score - partition;
            }
        }
    }
}

__global__ void crf_reduce(float* out) {
    int tid = threadIdx.x;  // 128 threads
    __shared__ float sh[4];
    float v = g_res[tid];
    #pragma unroll
    for (int msk = 16; msk >= 1; msk >>= 1)
        v += __shfl_xor_sync(0xffffffffu, v, msk);
    if ((tid & 31) == 0) sh[tid >> 5] = v;
    __syncthreads();
    if (tid == 0) out[0] = -(sh[0] + sh[1] + sh[2] + sh[3]);
}

extern "C" void kernel_launch(void* const* d_in, const int* in_sizes, int n_in,
                              void* d_out, int out_size) {
    (void)in_sizes; (void)n_in; (void)out_size;
    const float* em = (const float*)d_in[0];   // emissions [128,1024,128] f32
    const float* tr = (const float*)d_in[1];   // transition [128,128] f32
    const float* mk = (const float*)d_in[2];   // mask [128,1024] f32
    const int*   tg = (const int*)d_in[3];     // tags [128,1024] i32
    crf_fwd<<<B_N, NTH>>>(em, tr, mk, tg);
    crf_reduce<<<1, B_N>>>((float*)d_out);
}

// round 16
// speedup vs baseline: 1.0668x; 1.0027x over previous
#include <cuda_runtime.h>

#define B_N 128
#define S_N 1024
#define T_N 128
#define NTH 128
#define SOS_T 0
#define EOS_T 1

__device__ float g_res[B_N];

typedef unsigned long long u64;

static __device__ __forceinline__ u64 fma2(u64 a, u64 b, u64 c) {
    u64 d; asm("fma.rn.f32x2 %0, %1, %2, %3;" : "=l"(d) : "l"(a), "l"(b), "l"(c)); return d;
}
static __device__ __forceinline__ u64 add2(u64 a, u64 b) {
    u64 d; asm("add.rn.f32x2 %0, %1, %2;" : "=l"(d) : "l"(a), "l"(b)); return d;
}
static __device__ __forceinline__ u64 pk2(float x, float y) {
    u64 r; asm("mov.b64 %0, {%1,%2};" : "=l"(r) : "f"(x), "f"(y)); return r;
}
static __device__ __forceinline__ void upk2(u64 v, float &x, float &y) {
    asm("mov.b64 {%0,%1}, %2;" : "=f"(x), "=f"(y) : "l"(v));
}
static __device__ __forceinline__ float ex2a(float x) {
    float r; asm("ex2.approx.f32 %0, %1;" : "=f"(r) : "f"(x)); return r;
}
static __device__ __forceinline__ float lg2a(float x) {
    float r; asm("lg2.approx.f32 %0, %1;" : "=f"(r) : "f"(x)); return r;
}

// One CTA per batch, 128 threads, thread j owns column j of alpha.
// Linear-space recurrence. Normalizer chain: thread 2 publishes its raw wp each
// step; every thread reconstructs M_{s+1} = M_{s-1} + ln(wp_pub_{s-1}) at the
// TOP of step s (identical computation in all threads -> consistent chain,
// overlapped with the matvec). Alpha bookkeeping (lg2) is deferred one step,
// so the pre-barrier critical path is add-tree -> fmax -> FMUL -> STS.
__global__ void __launch_bounds__(NTH, 1) crf_fwd(
    const float* __restrict__ em, const float* __restrict__ tr,
    const float* __restrict__ mk, const int* __restrict__ tg)
{
    const int b = blockIdx.x;
    const int j = threadIdx.x;

    __shared__ __align__(16) float s_v[2][T_N];   // exp(alpha - M), double buffered
    __shared__ float s_wp[2];                     // published wp[2], double buffered
    __shared__ __align__(16) float s_red[NTH];
    __shared__ int   s_cnt[NTH];
    __shared__ float s_score;

    const float* emb = em + (size_t)b * S_N * T_N;
    const float* mkb = mk + (size_t)b * S_N;
    const int*   tgb = tg + (size_t)b * S_N;

    const float L2E = 1.4426950408889634f;
    const float LN2 = 0.6931471805599453f;

    // ---------------- gold path score ----------------
    {
        float sp = 0.f; int cnt = 0;
        for (int s = j; s < S_N; s += NTH) {
            float mv = mkb[s];
            cnt += (int)mv;
            if (s >= 1) {
                int t1  = tgb[s];
                int t0p = tgb[s - 1];
                sp += (emb[(size_t)s * T_N + t1] + tr[t0p * T_N + t1]) * mv;
            }
        }
        s_red[j] = sp; s_cnt[j] = cnt;
        __syncthreads();
        for (int st = NTH >> 1; st > 0; st >>= 1) {
            if (j < st) { s_red[j] += s_red[j + st]; s_cnt[j] += s_cnt[j + st]; }
            __syncthreads();
        }
        if (j == 0) {
            int last = s_cnt[0] - 1;
            int t0   = tgb[0];
            int lt   = tgb[last];
            s_score = s_red[0] + tr[SOS_T * T_N + t0] + emb[t0] + tr[lt * T_N + EOS_T];
        }
        __syncthreads();
    }

    // ---------------- transition column in registers (exp domain) ----------------
    // E[p] packs expT[2p][j], expT[2p+1][j]  (all 128 source states).
    u64 E[64];
    #pragma unroll
    for (int p = 0; p < 64; p++) {
        float a = ex2a(tr[(2 * p)     * T_N + j] * L2E);
        float c = ex2a(tr[(2 * p + 1) * T_N + j] * L2E);
        E[p] = pk2(a, c);
    }

    // ---------------- alpha0, m0, v0 ----------------
    float alpha = tr[SOS_T * T_N + j] + emb[j];
    s_red[j] = alpha;
    __syncthreads();
    if (j < 32) {
        float mx = fmaxf(fmaxf(s_red[j], s_red[j + 32]),
                         fmaxf(s_red[j + 64], s_red[j + 96]));
        #pragma unroll
        for (int msk = 16; msk >= 1; msk >>= 1)
            mx = fmaxf(mx, __shfl_xor_sync(0xffffffffu, mx, msk));
        if (j == 0) s_red[0] = mx;   // reuse s_red[0] to broadcast m0
    }
    __syncthreads();
    const float m0 = s_red[0];
    // M chain: M_cur = M_1 = m0; M_prev seeds M_2 = M_prev + ln(1) = m0.
    float M_prev = m0, M_cur = m0;
    s_v[1][j] = ex2a((alpha - m0) * L2E);   // step 1 reads buffer 1
    if (j == 0) s_wp[0] = 1.0f;             // step 1 reads slot 0

    // emission/mask register prefetch, distance 3
    float eA = emb[(size_t)1 * T_N + j];  float mA = mkb[1];
    float eB = emb[(size_t)2 * T_N + j];  float mB = mkb[2];
    float eC = emb[(size_t)3 * T_N + j];  float mC = mkb[3];

    // deferred-alpha state (step 0 already final: mP = 0 -> no-op update)
    float wp_prev = 1.0f, eP = 0.0f, mP = 0.0f, MP = m0;
    __syncthreads();

    // ---------------- recurrence: 1023 sequential steps ----------------
    for (int s = 1; s < S_N; s++) {
        // ===== overlapped top section (hidden under the matvec) =====
        float wp_pub = s_wp[(s - 1) & 1];
        float M_next = fmaf(lg2a(wp_pub), LN2, M_prev);  // M_{s+1}, thread-uniform
        // deferred alpha update for step s-1
        float anew_p = fmaf(lg2a(wp_prev), LN2, MP) + eP;
        alpha = fmaf(mP, anew_p - alpha, alpha);         // alpha_{s-1}
        float Kf    = ex2a((M_cur + eA - M_next) * L2E); // exp(M_s + e_s - M_{s+1})
        float v_old = ex2a((alpha - M_next) * L2E);      // mask==0 fallback
        int sp3 = (s + 3 < S_N) ? (s + 3) : (S_N - 1);
        float eN = emb[(size_t)sp3 * T_N + j];
        float mN = mkb[sp3];

        // ===== matvec over ALL 128 states: wp = sum_i v[i]*expT[i][j] =====
        const ulonglong2* v2 = (const ulonglong2*)s_v[s & 1];
        u64 a0 = 0ull, a1 = 0ull, a2 = 0ull, a3 = 0ull;
        u64 a4 = 0ull, a5 = 0ull, a6 = 0ull, a7 = 0ull;
        #pragma unroll
        for (int k = 0; k < 16; k++) {
            ulonglong2 p = v2[2 * k];
            ulonglong2 q = v2[2 * k + 1];
            if ((k & 1) == 0) {
                a0 = fma2(E[4 * k + 0], p.x, a0);
                a1 = fma2(E[4 * k + 1], p.y, a1);
                a2 = fma2(E[4 * k + 2], q.x, a2);
                a3 = fma2(E[4 * k + 3], q.y, a3);
            } else {
                a4 = fma2(E[4 * k + 0], p.x, a4);
                a5 = fma2(E[4 * k + 1], p.y, a5);
                a6 = fma2(E[4 * k + 2], q.x, a6);
                a7 = fma2(E[4 * k + 3], q.y, a7);
            }
        }
        u64 t0 = add2(add2(a0, a1), add2(a2, a3));
        u64 t1 = add2(add2(a4, a5), add2(a6, a7));
        u64 tt = add2(t0, t1);
        float tx, ty; upk2(tt, tx, ty);
        float wp = fmaxf(tx + ty, 1e-33f);   // SOS column sums to 0; keep finite

        // ===== short pre-barrier tail =====
        float v_new = (mA != 0.f) ? (wp * Kf) : v_old;
        s_v[(s + 1) & 1][j] = v_new;
        if (j == 2) s_wp[s & 1] = wp;        // publish raw wp for M_{s+2}

        // save deferred state, shift pipelines
        wp_prev = wp; eP = eA; mP = mA; MP = M_cur;
        M_prev = M_cur; M_cur = M_next;
        eA = eB; eB = eC; eC = eN;
        mA = mB; mB = mC; mC = mN;
        __syncthreads();
    }

    // final deferred alpha update (step S_N-1)
    {
        float anew_p = fmaf(lg2a(wp_prev), LN2, MP) + eP;
        alpha = fmaf(mP, anew_p - alpha, alpha);
    }

    // ---------------- partition + per-batch result ----------------
    {
        s_red[j] = alpha + tr[j * T_N + EOS_T];
        __syncthreads();
        if (j < 32) {
            float z0 = s_red[j], z1 = s_red[j + 32], z2 = s_red[j + 64], z3 = s_red[j + 96];
            float mx = fmaxf(fmaxf(z0, z1), fmaxf(z2, z3));
            #pragma unroll
            for (int msk = 16; msk >= 1; msk >>= 1)
                mx = fmaxf(mx, __shfl_xor_sync(0xffffffffu, mx, msk));
            float sm = ex2a((z0 - mx) * L2E) + ex2a((z1 - mx) * L2E)
                     + ex2a((z2 - mx) * L2E) + ex2a((z3 - mx) * L2E);
            #pragma unroll
            for (int msk = 16; msk >= 1; msk >>= 1)
                sm += __shfl_xor_sync(0xffffffffu, sm, msk);
            if (j == 0) {
                float partition = mx + lg2a(sm) * LN2;
                g_res[b] = s_score - partition;
            }
        }
    }
}

__global__ void crf_reduce(float* out) {
    int tid = threadIdx.x;  // 128 threads
    __shared__ float sh[4];
    float v = g_res[tid];
    #pragma unroll
    for (int msk = 16; msk >= 1; msk >>= 1)
        v += __shfl_xor_sync(0xffffffffu, v, msk);
    if ((tid & 31) == 0) sh[tid >> 5] = v;
    __syncthreads();
    if (tid == 0) out[0] = -(sh[0] + sh[1] + sh[2] + sh[3]);
}

extern "C" void kernel_launch(void* const* d_in, const int* in_sizes, int n_in,
                              void* d_out, int out_size) {
    (void)in_sizes; (void)n_in; (void)out_size;
    const float* em = (const float*)d_in[0];   // emissions [128,1024,128] f32
    const float* tr = (const float*)d_in[1];   // transition [128,128] f32
    const float* mk = (const float*)d_in[2];   // mask [128,1024] f32
    const int*   tg = (const int*)d_in[3];     // tags [128,1024] i32
    crf_fwd<<<B_N, NTH>>>(em, tr, mk, tg);
    crf_reduce<<<1, B_N>>>((float*)d_out);
}

// round 17
// speedup vs baseline: 1.0714x; 1.0043x over previous
#include <cuda_runtime.h>

#define B_N 128
#define S_N 1024
#define T_N 128
#define NTH 128
#define SOS_T 0
#define EOS_T 1

__device__ float g_res[B_N];

typedef unsigned long long u64;

static __device__ __forceinline__ u64 fma2(u64 a, u64 b, u64 c) {
    u64 d; asm("fma.rn.f32x2 %0, %1, %2, %3;" : "=l"(d) : "l"(a), "l"(b), "l"(c)); return d;
}
static __device__ __forceinline__ u64 add2(u64 a, u64 b) {
    u64 d; asm("add.rn.f32x2 %0, %1, %2;" : "=l"(d) : "l"(a), "l"(b)); return d;
}
static __device__ __forceinline__ u64 pk2(float x, float y) {
    u64 r; asm("mov.b64 %0, {%1,%2};" : "=l"(r) : "f"(x), "f"(y)); return r;
}
static __device__ __forceinline__ void upk2(u64 v, float &x, float &y) {
    asm("mov.b64 {%0,%1}, %2;" : "=f"(x), "=f"(y) : "l"(v));
}
static __device__ __forceinline__ float ex2a(float x) {
    float r; asm("ex2.approx.f32 %0, %1;" : "=f"(r) : "f"(x)); return r;
}
static __device__ __forceinline__ float lg2a(float x) {
    float r; asm("lg2.approx.f32 %0, %1;" : "=f"(r) : "f"(x)); return r;
}

// One CTA per batch, 128 threads, thread j owns column j of alpha.
// Linear-space recurrence. Normalizer chain: thread 2 publishes its raw wp each
// step; every thread reconstructs M_{s+1} = M_{s-1} + ln(wp_pub_{s-1}) at the
// TOP of step s (identical computation in all threads -> consistent chain,
// overlapped with the matvec). Alpha bookkeeping (lg2) is deferred one step,
// so the pre-barrier critical path is add-tree -> fmax -> FMUL -> STS.
__global__ void __launch_bounds__(NTH, 1) crf_fwd(
    const float* __restrict__ em, const float* __restrict__ tr,
    const float* __restrict__ mk, const int* __restrict__ tg)
{
    const int b = blockIdx.x;
    const int j = threadIdx.x;

    __shared__ __align__(16) float s_v[2][T_N];   // exp(alpha - M), double buffered
    __shared__ float s_wp[2];                     // published wp[2], double buffered
    __shared__ __align__(16) float s_red[NTH];
    __shared__ int   s_cnt[NTH];
    __shared__ float s_score;

    const float* emb = em + (size_t)b * S_N * T_N;
    const float* mkb = mk + (size_t)b * S_N;
    const int*   tgb = tg + (size_t)b * S_N;

    const float L2E = 1.4426950408889634f;
    const float LN2 = 0.6931471805599453f;

    // ---------------- gold path score ----------------
    {
        float sp = 0.f; int cnt = 0;
        for (int s = j; s < S_N; s += NTH) {
            float mv = mkb[s];
            cnt += (int)mv;
            if (s >= 1) {
                int t1  = tgb[s];
                int t0p = tgb[s - 1];
                sp += (emb[(size_t)s * T_N + t1] + tr[t0p * T_N + t1]) * mv;
            }
        }
        s_red[j] = sp; s_cnt[j] = cnt;
        __syncthreads();
        for (int st = NTH >> 1; st > 0; st >>= 1) {
            if (j < st) { s_red[j] += s_red[j + st]; s_cnt[j] += s_cnt[j + st]; }
            __syncthreads();
        }
        if (j == 0) {
            int last = s_cnt[0] - 1;
            int t0   = tgb[0];
            int lt   = tgb[last];
            s_score = s_red[0] + tr[SOS_T * T_N + t0] + emb[t0] + tr[lt * T_N + EOS_T];
        }
        __syncthreads();
    }

    // ---------------- transition column in registers (exp domain) ----------------
    // E[p] packs expT[2p][j], expT[2p+1][j]  (all 128 source states).
    u64 E[64];
    #pragma unroll
    for (int p = 0; p < 64; p++) {
        float a = ex2a(tr[(2 * p)     * T_N + j] * L2E);
        float c = ex2a(tr[(2 * p + 1) * T_N + j] * L2E);
        E[p] = pk2(a, c);
    }

    // ---------------- alpha0, m0, v0 ----------------
    float alpha = tr[SOS_T * T_N + j] + emb[j];
    s_red[j] = alpha;
    __syncthreads();
    if (j < 32) {
        float mx = fmaxf(fmaxf(s_red[j], s_red[j + 32]),
                         fmaxf(s_red[j + 64], s_red[j + 96]));
        #pragma unroll
        for (int msk = 16; msk >= 1; msk >>= 1)
            mx = fmaxf(mx, __shfl_xor_sync(0xffffffffu, mx, msk));
        if (j == 0) s_red[0] = mx;   // reuse s_red[0] to broadcast m0
    }
    __syncthreads();
    const float m0 = s_red[0];
    // M chain: M_cur = M_1 = m0; M_prev seeds M_2 = M_prev + ln(1) = m0.
    float M_prev = m0, M_cur = m0;
    s_v[1][j] = ex2a((alpha - m0) * L2E);   // step 1 reads buffer 1
    if (j == 0) s_wp[0] = 1.0f;             // step 1 reads slot 0

    // emission/mask register prefetch, distance 3
    float eA = emb[(size_t)1 * T_N + j];  float mA = mkb[1];
    float eB = emb[(size_t)2 * T_N + j];  float mB = mkb[2];
    float eC = emb[(size_t)3 * T_N + j];  float mC = mkb[3];

    // deferred-alpha state (step 0 already final: mP = 0 -> no-op update)
    float wp_prev = 1.0f, eP = 0.0f, mP = 0.0f, MP = m0;
    __syncthreads();

    // ---------------- recurrence: 1023 sequential steps ----------------
    for (int s = 1; s < S_N; s++) {
        // ===== overlapped top section (hidden under the matvec) =====
        float wp_pub = s_wp[(s - 1) & 1];
        float M_next = fmaf(lg2a(wp_pub), LN2, M_prev);  // M_{s+1}, thread-uniform
        // deferred alpha update for step s-1
        float anew_p = fmaf(lg2a(wp_prev), LN2, MP) + eP;
        alpha = fmaf(mP, anew_p - alpha, alpha);         // alpha_{s-1}
        float Kf    = ex2a((M_cur + eA - M_next) * L2E); // exp(M_s + e_s - M_{s+1})
        float v_old = ex2a((alpha - M_next) * L2E);      // mask==0 fallback
        int sp3 = (s + 3 < S_N) ? (s + 3) : (S_N - 1);
        float eN = emb[(size_t)sp3 * T_N + j];
        float mN = mkb[sp3];

        // ===== matvec over ALL 128 states: wp = sum_i v[i]*expT[i][j] =====
        const ulonglong2* v2 = (const ulonglong2*)s_v[s & 1];
        u64 a0 = 0ull, a1 = 0ull, a2 = 0ull, a3 = 0ull;
        u64 a4 = 0ull, a5 = 0ull, a6 = 0ull, a7 = 0ull;
        #pragma unroll
        for (int k = 0; k < 16; k++) {
            ulonglong2 p = v2[2 * k];
            ulonglong2 q = v2[2 * k + 1];
            if ((k & 1) == 0) {
                a0 = fma2(E[4 * k + 0], p.x, a0);
                a1 = fma2(E[4 * k + 1], p.y, a1);
                a2 = fma2(E[4 * k + 2], q.x, a2);
                a3 = fma2(E[4 * k + 3], q.y, a3);
            } else {
                a4 = fma2(E[4 * k + 0], p.x, a4);
                a5 = fma2(E[4 * k + 1], p.y, a5);
                a6 = fma2(E[4 * k + 2], q.x, a6);
                a7 = fma2(E[4 * k + 3], q.y, a7);
            }
        }
        u64 t0 = add2(add2(a0, a1), add2(a2, a3));
        u64 t1 = add2(add2(a4, a5), add2(a6, a7));
        u64 tt = add2(t0, t1);
        float tx, ty; upk2(tt, tx, ty);
        float wp = fmaxf(tx + ty, 1e-33f);   // SOS column sums to 0; keep finite

        // ===== short pre-barrier tail =====
        float v_new = (mA != 0.f) ? (wp * Kf) : v_old;
        s_v[(s + 1) & 1][j] = v_new;
        if (j == 2) s_wp[s & 1] = wp;        // publish raw wp for M_{s+2}

        // save deferred state, shift pipelines
        wp_prev = wp; eP = eA; mP = mA; MP = M_cur;
        M_prev = M_cur; M_cur = M_next;
        eA = eB; eB = eC; eC = eN;
        mA = mB; mB = mC; mC = mN;
        __syncthreads();
    }

    // final deferred alpha update (step S_N-1)
    {
        float anew_p = fmaf(lg2a(wp_prev), LN2, MP) + eP;
        alpha = fmaf(mP, anew_p - alpha, alpha);
    }

    // ---------------- partition + per-batch result ----------------
    {
        s_red[j] = alpha + tr[j * T_N + EOS_T];
        __syncthreads();
        if (j < 32) {
            float z0 = s_red[j], z1 = s_red[j + 32], z2 = s_red[j + 64], z3 = s_red[j + 96];
            float mx = fmaxf(fmaxf(z0, z1), fmaxf(z2, z3));
            #pragma unroll
            for (int msk = 16; msk >= 1; msk >>= 1)
                mx = fmaxf(mx, __shfl_xor_sync(0xffffffffu, mx, msk));
            float sm = ex2a((z0 - mx) * L2E) + ex2a((z1 - mx) * L2E)
                     + ex2a((z2 - mx) * L2E) + ex2a((z3 - mx) * L2E);
            #pragma unroll
            for (int msk = 16; msk >= 1; msk >>= 1)
                sm += __shfl_xor_sync(0xffffffffu, sm, msk);
            if (j == 0) {
                float partition = mx + lg2a(sm) * LN2;
                g_res[b] = s_score - partition;
            }
        }
    }
}

__global__ void crf_reduce(float* out) {
    int tid = threadIdx.x;  // 128 threads
    __shared__ float sh[4];
    float v = g_res[tid];
    #pragma unroll
    for (int msk = 16; msk >= 1; msk >>= 1)
        v += __shfl_xor_sync(0xffffffffu, v, msk);
    if ((tid & 31) == 0) sh[tid >> 5] = v;
    __syncthreads();
    if (tid == 0) out[0] = -(sh[0] + sh[1] + sh[2] + sh[3]);
}

extern "C" void kernel_launch(void* const* d_in, const int* in_sizes, int n_in,
                              void* d_out, int out_size) {
    (void)in_sizes; (void)n_in; (void)out_size;
    const float* em = (const float*)d_in[0];   // emissions [128,1024,128] f32
    const float* tr = (const float*)d_in[1];   // transition [128,128] f32
    const float* mk = (const float*)d_in[2];   // mask [128,1024] f32
    const int*   tg = (const int*)d_in[3];     // tags [128,1024] i32
    crf_fwd<<<B_N, NTH>>>(em, tr, mk, tg);
    crf_reduce<<<1, B_N>>>((float*)d_out);
}